// round 2
// baseline (speedup 1.0000x reference)
#include <cuda_runtime.h>
#include <cuda_bf16.h>
#include <cstdint>

// Problem constants (fixed by the reference: NUM_GRAPHS=1024, F_DIM=512)
#define F_DIM   512
#define F4      (F_DIM / 4)     // 128 float4 per row
#define NGROUPS 1024
#define NPB     64              // nodes per block in the accumulate phase
#define OUTK    7

// Scratch: static device arrays (no allocations allowed)
__device__ float g_sums[NGROUPS * F_DIM];   // 2 MB
__device__ float g_cnt[NGROUPS];
__device__ int   g_batch_is64;              // dtype probe result

// ---------------------------------------------------------------------------
// Kernel 0: probe batch dtype. batch is sorted 0..1023, so its final element
// is nonzero. Viewed as 32-bit words within the guaranteed N*4 bytes:
//   int64 storage -> odd word indices are high words == 0
//   int32 storage -> word[N-1] == max group id != 0
// ---------------------------------------------------------------------------
__global__ void probe_kernel(const int* __restrict__ bw, int N) {
    // check three odd-index words near the end; all zero => int64
    int z = (bw[N - 1] == 0) + (bw[N - 3] == 0) + (bw[N - 5] == 0);
    g_batch_is64 = (z == 3) ? 1 : 0;
}

// ---------------------------------------------------------------------------
// Kernel 1: zero the scratch accumulators (graph replays need this each launch)
// ---------------------------------------------------------------------------
__global__ void zero_kernel() {
    int i = blockIdx.x * blockDim.x + threadIdx.x;
    if (i < NGROUPS * F_DIM) g_sums[i] = 0.0f;
    if (i < NGROUPS)         g_cnt[i]  = 0.0f;
}

// ---------------------------------------------------------------------------
// Kernel 2: segment-sum of x into g_sums, counts into g_cnt.
// Block = 128 threads, owns NPB consecutive nodes. Thread t owns columns
// [4t, 4t+4). Running register accumulator per group run (batch is sorted),
// flushed with atomics only on group boundaries.
// ---------------------------------------------------------------------------
__global__ __launch_bounds__(128)
void accum_kernel(const float4* __restrict__ x4,
                  const int* __restrict__ bw,   // batch as 32-bit words
                  int N)
{
    __shared__ int sgid[NPB];
    const int n0   = blockIdx.x * NPB;
    const int nCnt = min(NPB, N - n0);
    if (nCnt <= 0) return;
    const int t = threadIdx.x;
    const int is64 = g_batch_is64;

    // Preload group ids for this node span (uniform across the block)
    for (int i = t; i < nCnt; i += 128) {
        int g = is64 ? bw[2 * (n0 + i)] : bw[n0 + i];
        // clamp defensively (never fires when decode is correct)
        sgid[i] = min(max(g, 0), NGROUPS - 1);
    }
    __syncthreads();

    float4 acc = make_float4(0.f, 0.f, 0.f, 0.f);
    int cur = sgid[0];
    int run = 0;

    #pragma unroll 4
    for (int i = 0; i < nCnt; i++) {
        int g = sgid[i];
        if (g != cur) {
            // flush current run (rare: ~2x per block)
            float* dst = g_sums + (size_t)cur * F_DIM + 4 * t;
            atomicAdd(dst + 0, acc.x);
            atomicAdd(dst + 1, acc.y);
            atomicAdd(dst + 2, acc.z);
            atomicAdd(dst + 3, acc.w);
            if (t == 0) atomicAdd(&g_cnt[cur], (float)run);
            acc = make_float4(0.f, 0.f, 0.f, 0.f);
            cur = g;
            run = 0;
        }
        float4 v = x4[(size_t)(n0 + i) * F4 + t];
        acc.x += v.x; acc.y += v.y; acc.z += v.z; acc.w += v.w;
        run++;
    }

    // final flush
    float* dst = g_sums + (size_t)cur * F_DIM + 4 * t;
    atomicAdd(dst + 0, acc.x);
    atomicAdd(dst + 1, acc.y);
    atomicAdd(dst + 2, acc.z);
    atomicAdd(dst + 3, acc.w);
    if (t == 0) atomicAdd(&g_cnt[cur], (float)run);
}

// ---------------------------------------------------------------------------
// Kernel 3: out[g][k] = dot(g_sums[g], W[k]) / max(cnt[g],1) + b[k]
// One block (128 threads) per group.
// ---------------------------------------------------------------------------
__global__ __launch_bounds__(128)
void finalize_kernel(const float4* __restrict__ W4,   // [7][128] float4
                     const float*  __restrict__ b,
                     float* __restrict__ out)
{
    const int g = blockIdx.x;
    const int t = threadIdx.x;

    float4 s = ((const float4*)g_sums)[(size_t)g * F4 + t];

    float p[OUTK];
    #pragma unroll
    for (int k = 0; k < OUTK; k++) {
        float4 w = W4[k * F4 + t];
        p[k] = s.x * w.x + s.y * w.y + s.z * w.z + s.w * w.w;
    }

    // warp reduction
    #pragma unroll
    for (int off = 16; off > 0; off >>= 1) {
        #pragma unroll
        for (int k = 0; k < OUTK; k++)
            p[k] += __shfl_xor_sync(0xffffffff, p[k], off);
    }

    __shared__ float red[4][OUTK];
    const int warp = t >> 5, lane = t & 31;
    if (lane == 0) {
        #pragma unroll
        for (int k = 0; k < OUTK; k++) red[warp][k] = p[k];
    }
    __syncthreads();

    if (t < OUTK) {
        float v = red[0][t] + red[1][t] + red[2][t] + red[3][t];
        float c = g_cnt[g];
        out[g * OUTK + t] = v / fmaxf(c, 1.0f) + b[t];
    }
}

// ---------------------------------------------------------------------------
// Launch. Inputs (metadata order):
//   d_in[0] = x          float32 [100000, 512]
//   d_in[1] = edge_index (unused)
//   d_in[2] = edge_attr  (unused)
//   d_in[3] = batch_size int64-or-int32 [100000]  (probed at runtime)
//   d_in[4] = W          float32 [7, 512]
//   d_in[5] = b          float32 [7]
// Output: float32 [1024, 7]
// ---------------------------------------------------------------------------
extern "C" void kernel_launch(void* const* d_in, const int* in_sizes, int n_in,
                              void* d_out, int out_size)
{
    const float4* x4  = (const float4*)d_in[0];
    const int*    bw  = (const int*)d_in[3];
    const float4* W4  = (const float4*)d_in[4];
    const float*  b   = (const float*)d_in[5];
    float*        out = (float*)d_out;

    const int N = in_sizes[3];

    // 0) probe batch dtype (1 thread, trivial)
    probe_kernel<<<1, 1>>>(bw, N);

    // 1) zero scratch
    {
        int total = NGROUPS * F_DIM;
        int threads = 256;
        int blocks = (total + threads - 1) / threads;
        zero_kernel<<<blocks, threads>>>();
    }

    // 2) segment sum
    {
        int blocks = (N + NPB - 1) / NPB;
        accum_kernel<<<blocks, 128>>>(x4, bw, N);
    }

    // 3) pooled @ W.T + b
    finalize_kernel<<<NGROUPS, 128>>>(W4, b, out);
}